// round 1
// baseline (speedup 1.0000x reference)
#include <cuda_runtime.h>
#include <math.h>

#define B_  4
#define S_  1024
#define D_  512
#define H_  8
#define DH_ 64
#define SCALE_ 0.125f   // DH^-0.5

// Scratch (device globals: allocation-free per harness rules)
__device__ float g_Q[B_*H_*S_*DH_];
__device__ float g_K[B_*H_*S_*DH_];
__device__ float g_V[B_*H_*S_*DH_];
__device__ float g_C[B_*S_*D_];

// ---------------------------------------------------------------------------
// GEMM: out = X[4096,512] @ W[512,512]; headed=1 scatters to [B,H,S,DH]
// ---------------------------------------------------------------------------
__global__ __launch_bounds__(256) void gemm512(const float* __restrict__ X,
                                               const float* __restrict__ W,
                                               float* __restrict__ out,
                                               int headed)
{
    __shared__ float As[16][68];
    __shared__ float Bs[16][68];
    const int m0 = blockIdx.y * 64;
    const int n0 = blockIdx.x * 64;
    const int tid = threadIdx.x;
    const int ty = tid >> 4, tx = tid & 15;
    const int arow = tid >> 2, acol = (tid & 3) * 4;
    const int brow = tid >> 4, bcol = (tid & 15) * 4;

    float acc[4][4] = {};

    for (int k0 = 0; k0 < 512; k0 += 16) {
        float4 av = *(const float4*)&X[(m0 + arow) * 512 + k0 + acol];
        float4 bv = *(const float4*)&W[(k0 + brow) * 512 + n0 + bcol];
        __syncthreads();
        As[acol + 0][arow] = av.x;
        As[acol + 1][arow] = av.y;
        As[acol + 2][arow] = av.z;
        As[acol + 3][arow] = av.w;
        *(float4*)&Bs[brow][bcol] = bv;
        __syncthreads();
#pragma unroll
        for (int kk = 0; kk < 16; kk++) {
            float4 a4 = *(const float4*)&As[kk][ty * 4];
            float4 b4 = *(const float4*)&Bs[kk][tx * 4];
            float a_[4] = {a4.x, a4.y, a4.z, a4.w};
            float b_[4] = {b4.x, b4.y, b4.z, b4.w};
#pragma unroll
            for (int r = 0; r < 4; r++)
#pragma unroll
                for (int c = 0; c < 4; c++)
                    acc[r][c] += a_[r] * b_[c];
        }
    }

    if (headed) {
        const int hh = n0 >> 6;  // N=512 -> head = blockIdx.x
#pragma unroll
        for (int r = 0; r < 4; r++) {
            int m = m0 + ty * 4 + r;
            int bi = m >> 10, si = m & 1023;
            float4 o = make_float4(acc[r][0], acc[r][1], acc[r][2], acc[r][3]);
            *(float4*)&out[((bi * H_ + hh) * S_ + si) * DH_ + tx * 4] = o;
        }
    } else {
#pragma unroll
        for (int r = 0; r < 4; r++) {
            float4 o = make_float4(acc[r][0], acc[r][1], acc[r][2], acc[r][3]);
            *(float4*)&out[(m0 + ty * 4 + r) * 512 + n0 + tx * 4] = o;
        }
    }
}

// ---------------------------------------------------------------------------
// Fused causal attention with skewed relative bias.
// bias(i,j) = q_i . rel[:, S-1-i+j]  for j <= i  (derived from the skew trick)
// Flash-style: 64-row q tile per block, online softmax over key tiles.
// ---------------------------------------------------------------------------
__device__ __forceinline__ float rmax16(float v) {
#pragma unroll
    for (int o = 8; o; o >>= 1) v = fmaxf(v, __shfl_xor_sync(0xffffffffu, v, o, 16));
    return v;
}
__device__ __forceinline__ float rsum16(float v) {
#pragma unroll
    for (int o = 8; o; o >>= 1) v += __shfl_xor_sync(0xffffffffu, v, o, 16);
    return v;
}

#define QS(d, i) Qs[(d) * 68 + (i)]
#define KS(d, j) Ks[(d) * 68 + (j)]
#define VS(j, d) Vs[(j) * 68 + (d)]
#define PS(i, j) Ps[(i) * 68 + (j)]
#define RS(d, l) Rs[(d) * 132 + (l)]
#define ATTN_SMEM_BYTES ((4 * 64 * 68 + 64 * 132) * 4)   // 103424 B

__global__ __launch_bounds__(256, 2) void attn_kernel(const float* __restrict__ Q,
                                                      const float* __restrict__ K,
                                                      const float* __restrict__ V,
                                                      const float* __restrict__ rel,
                                                      float* __restrict__ ctx)
{
    extern __shared__ float sm[];
    float* Qs = sm;                 // [64][68] transposed: Qs[d][i]
    float* Ks = Qs + 64 * 68;       // [64][68] transposed: Ks[d][j]
    float* Vs = Ks + 64 * 68;       // [64][68] direct:     Vs[j][d]
    float* Ps = Vs + 64 * 68;       // [64][68] probs:      Ps[i][j]
    float* Rs = Ps + 64 * 68;       // [64][132] rel tile:  Rs[d][lc]

    const int qt = (int)gridDim.x - 1 - (int)blockIdx.x;  // heavy tiles first
    const int h = blockIdx.y, b = blockIdx.z;
    const int i0 = qt * 64;
    const int tid = threadIdx.x;
    const int ty = tid >> 4, tx = tid & 15;

    const float* Qb = Q + (size_t)(b * H_ + h) * S_ * DH_;
    const float* Kb = K + (size_t)(b * H_ + h) * S_ * DH_;
    const float* Vb = V + (size_t)(b * H_ + h) * S_ * DH_;
    const float* relh = rel + (size_t)h * DH_ * S_;

    // Load Q tile (transposed)
#pragma unroll
    for (int rep = 0; rep < 4; rep++) {
        int lin = rep * 256 + tid;
        int i = lin >> 4, sd = (lin & 15) * 4;
        float4 v = *(const float4*)&Qb[(i0 + i) * DH_ + sd];
        QS(sd + 0, i) = v.x; QS(sd + 1, i) = v.y;
        QS(sd + 2, i) = v.z; QS(sd + 3, i) = v.w;
    }

    float mrow[4], lrow[4], acc[4][4];
#pragma unroll
    for (int r = 0; r < 4; r++) {
        mrow[r] = -1e30f;
        lrow[r] = 0.f;
#pragma unroll
        for (int c = 0; c < 4; c++) acc[r][c] = 0.f;
    }

    const int bm3 = 60 + 4 * tx - 4 * ty;  // lc index of rv[0]

    for (int jt = 0; jt <= qt; jt++) {
        const int j0 = jt * 64;
        __syncthreads();  // protect Ps/Vs reads of previous iteration

        // Load K (transposed) and V (direct)
#pragma unroll
        for (int rep = 0; rep < 4; rep++) {
            int lin = rep * 256 + tid;
            int j = lin >> 4, sd = (lin & 15) * 4;
            float4 kv = *(const float4*)&Kb[(j0 + j) * DH_ + sd];
            KS(sd + 0, j) = kv.x; KS(sd + 1, j) = kv.y;
            KS(sd + 2, j) = kv.z; KS(sd + 3, j) = kv.w;
            float4 vv = *(const float4*)&Vb[(j0 + j) * DH_ + sd];
            *(float4*)&VS(j, sd) = vv;
        }
        // Load rel tile: columns cbase..cbase+127 of rel[h]
        {
            const int cbase = S_ - 64 - i0 + j0;
#pragma unroll
            for (int rep = 0; rep < 32; rep++) {
                int lin = rep * 256 + tid;
                int d = lin >> 7, lc = lin & 127;
                int c = cbase + lc;
                RS(d, lc) = (c >= 0 && c < S_) ? relh[d * S_ + c] : 0.f;
            }
        }
        __syncthreads();

        // S tile: s = q.(k + rel_shifted)
        float s[4][4] = {};
#pragma unroll 8
        for (int d = 0; d < 64; d++) {
            float a_[4], k_[4], rv[7];
#pragma unroll
            for (int r = 0; r < 4; r++) a_[r] = QS(d, ty * 4 + r);
#pragma unroll
            for (int c = 0; c < 4; c++) k_[c] = KS(d, tx * 4 + c);
#pragma unroll
            for (int u = 0; u < 7; u++) rv[u] = RS(d, bm3 + u);
#pragma unroll
            for (int r = 0; r < 4; r++)
#pragma unroll
                for (int c = 0; c < 4; c++)
                    s[r][c] += a_[r] * (k_[c] + rv[3 + c - r]);
        }

        // Causal mask + scale
#pragma unroll
        for (int r = 0; r < 4; r++) {
            int gi = i0 + ty * 4 + r;
#pragma unroll
            for (int c = 0; c < 4; c++) {
                int gj = j0 + tx * 4 + c;
                s[r][c] = (gj > gi) ? -INFINITY : s[r][c] * SCALE_;
            }
        }

        // Online softmax update
#pragma unroll
        for (int r = 0; r < 4; r++) {
            float tm = fmaxf(fmaxf(s[r][0], s[r][1]), fmaxf(s[r][2], s[r][3]));
            tm = rmax16(tm);
            float nm = fmaxf(mrow[r], tm);
            float al = __expf(mrow[r] - nm);
            float p0 = __expf(s[r][0] - nm);
            float p1 = __expf(s[r][1] - nm);
            float p2 = __expf(s[r][2] - nm);
            float p3 = __expf(s[r][3] - nm);
            float rs = rsum16(p0 + p1 + p2 + p3);
            lrow[r] = lrow[r] * al + rs;
            mrow[r] = nm;
#pragma unroll
            for (int c = 0; c < 4; c++) acc[r][c] *= al;
            PS(ty * 4 + r, tx * 4 + 0) = p0;
            PS(ty * 4 + r, tx * 4 + 1) = p1;
            PS(ty * 4 + r, tx * 4 + 2) = p2;
            PS(ty * 4 + r, tx * 4 + 3) = p3;
        }
        __syncthreads();

        // acc += P @ V
#pragma unroll 8
        for (int j = 0; j < 64; j++) {
            float p_[4];
#pragma unroll
            for (int r = 0; r < 4; r++) p_[r] = PS(ty * 4 + r, j);
            float4 v4 = *(const float4*)&VS(j, tx * 4);
            float v_[4] = {v4.x, v4.y, v4.z, v4.w};
#pragma unroll
            for (int r = 0; r < 4; r++)
#pragma unroll
                for (int c = 0; c < 4; c++)
                    acc[r][c] += p_[r] * v_[c];
        }
    }

    // Write ctx in [B, S, H*DH] layout for the output projection GEMM
#pragma unroll
    for (int r = 0; r < 4; r++) {
        float inv = 1.f / lrow[r];
        int gi = i0 + ty * 4 + r;
        float4 o = make_float4(acc[r][0] * inv, acc[r][1] * inv,
                               acc[r][2] * inv, acc[r][3] * inv);
        *(float4*)&g_C[((size_t)b * S_ + gi) * D_ + h * DH_ + tx * 4] = o;
    }
}

// ---------------------------------------------------------------------------
extern "C" void kernel_launch(void* const* d_in, const int* in_sizes, int n_in,
                              void* d_out, int out_size)
{
    (void)in_sizes; (void)n_in; (void)out_size;
    const float* queries = (const float*)d_in[0];
    const float* keys    = (const float*)d_in[1];
    const float* values  = (const float*)d_in[2];
    // d_in[3] = mask: causal, implemented analytically
    const float* Wq = (const float*)d_in[4];
    const float* Wk = (const float*)d_in[5];
    const float* Wv = (const float*)d_in[6];
    const float* Wo = (const float*)d_in[7];
    const float* rel = (const float*)d_in[8];

    float *Qp, *Kp, *Vp, *Cp;
    cudaGetSymbolAddress((void**)&Qp, g_Q);
    cudaGetSymbolAddress((void**)&Kp, g_K);
    cudaGetSymbolAddress((void**)&Vp, g_V);
    cudaGetSymbolAddress((void**)&Cp, g_C);

    cudaFuncSetAttribute(attn_kernel, cudaFuncAttributeMaxDynamicSharedMemorySize,
                         ATTN_SMEM_BYTES);

    dim3 gg(8, 64);  // N/64, M/64
    gemm512<<<gg, 256>>>(queries, Wq, Qp, 1);
    gemm512<<<gg, 256>>>(keys,    Wk, Kp, 1);
    gemm512<<<gg, 256>>>(values,  Wv, Vp, 1);
    attn_kernel<<<dim3(16, H_, B_), 256, ATTN_SMEM_BYTES>>>(Qp, Kp, Vp, rel, Cp);
    gemm512<<<gg, 256>>>(Cp, Wo, (float*)d_out, 0);
}

// round 4
// speedup vs baseline: 1.1880x; 1.1880x over previous
#include <cuda_runtime.h>
#include <math.h>
#include <stdint.h>

#define B_  4
#define S_  1024
#define D_  512
#define H_  8
#define DH_ 64
#define SCALE_ 0.125f   // DH^-0.5

typedef unsigned long long u64;

// Scratch (device globals: allocation-free per harness rules)
__device__ float g_Q[B_*H_*S_*DH_];
__device__ float g_K[B_*H_*S_*DH_];
__device__ float g_V[B_*H_*S_*DH_];
__device__ float g_C[B_*S_*D_];

// ---------------------------------------------------------------------------
// Packed f32x2 helpers (Blackwell sm_103a)
// ---------------------------------------------------------------------------
__device__ __forceinline__ u64 pack2(float lo, float hi) {
    u64 r; asm("mov.b64 %0, {%1, %2};" : "=l"(r) : "f"(lo), "f"(hi)); return r;
}
__device__ __forceinline__ u64 dup2(float x) { return pack2(x, x); }
__device__ __forceinline__ void unpack2(u64 v, float& lo, float& hi) {
    asm("mov.b64 {%0, %1}, %2;" : "=f"(lo), "=f"(hi) : "l"(v));
}
__device__ __forceinline__ u64 fma2(u64 a, u64 b, u64 c) {
    u64 d; asm("fma.rn.f32x2 %0, %1, %2, %3;" : "=l"(d) : "l"(a), "l"(b), "l"(c));
    return d;
}
__device__ __forceinline__ u64 add2(u64 a, u64 b) {
    u64 d; asm("add.rn.f32x2 %0, %1, %2;" : "=l"(d) : "l"(a), "l"(b)); return d;
}
__device__ __forceinline__ u64 mul2(u64 a, u64 b) {
    u64 d; asm("mul.rn.f32x2 %0, %1, %2;" : "=l"(d) : "l"(a), "l"(b)); return d;
}

// ===========================================================================
// SIMT f32x2 GEMM: out[4096,512] = X[4096,512] @ W[512,512]
// 128x128 tile, 8x8 micro-tile (f32x2-packed cols), K-chunk 16, double buffer.
// headed=1 scatters out to [B,H,S,DH]; grid.z selects (X,W,O) triple.
// ===========================================================================
#define NCH 32   // 512 / 16

__global__ __launch_bounds__(256) void gemm_f2(
    const float* __restrict__ X0, const float* __restrict__ X1,
    const float* __restrict__ X2,
    const float* __restrict__ W0, const float* __restrict__ W1,
    const float* __restrict__ W2,
    float* __restrict__ O0, float* __restrict__ O1,
    float* __restrict__ O2, int headed)
{
    __shared__ __align__(16) float As[2][16][132];   // As[buf][k][row]
    __shared__ __align__(16) float Bs[2][16][132];   // Bs[buf][k][col]

    const int z = blockIdx.z;
    const float* X = (z == 0) ? X0 : (z == 1) ? X1 : X2;
    const float* W = (z == 0) ? W0 : (z == 1) ? W1 : W2;
    float* O       = (z == 0) ? O0 : (z == 1) ? O1 : O2;

    const int m0 = blockIdx.y * 128;
    const int n0 = blockIdx.x * 128;
    const int tid = threadIdx.x;
    const int ty = tid >> 4, tx = tid & 15;

    // A loader: 2 float4/thread, row = lin>>2, kq = (lin&3)*4
    const int a_row0 = tid >> 2,        a_kq = (tid & 3) * 4;
    // B loader: 2 float4/thread, bk = lin>>5, bn = (lin&31)*4
    const int b_k0 = tid >> 5,          b_n = (tid & 31) * 4;

    u64 acc[8][4];
#pragma unroll
    for (int r = 0; r < 8; r++)
#pragma unroll
        for (int cp = 0; cp < 4; cp++) acc[r][cp] = 0ull;

    float4 ra[2], rb[2];
    // prologue: load chunk 0
#pragma unroll
    for (int it = 0; it < 2; it++) {
        ra[it] = *(const float4*)&X[(m0 + a_row0 + it * 64) * 512 + a_kq];
        rb[it] = *(const float4*)&W[(b_k0 + it * 8) * 512 + n0 + b_n];
    }
#pragma unroll
    for (int it = 0; it < 2; it++) {
        int row = a_row0 + it * 64;
        As[0][a_kq + 0][row] = ra[it].x;
        As[0][a_kq + 1][row] = ra[it].y;
        As[0][a_kq + 2][row] = ra[it].z;
        As[0][a_kq + 3][row] = ra[it].w;
        *(float4*)&Bs[0][b_k0 + it * 8][b_n] = rb[it];
    }

    for (int c = 0; c < NCH; c++) {
        __syncthreads();
        const int buf = c & 1;
        if (c < NCH - 1) {
            const int k0 = (c + 1) * 16;
#pragma unroll
            for (int it = 0; it < 2; it++) {
                ra[it] = *(const float4*)&X[(m0 + a_row0 + it * 64) * 512 + k0 + a_kq];
                rb[it] = *(const float4*)&W[(k0 + b_k0 + it * 8) * 512 + n0 + b_n];
            }
        }
#pragma unroll
        for (int kk = 0; kk < 16; kk++) {
            float4 a0 = *(const float4*)&As[buf][kk][ty * 4];
            float4 a1 = *(const float4*)&As[buf][kk][64 + ty * 4];
            ulonglong2 bl = *(const ulonglong2*)&Bs[buf][kk][tx * 4];
            ulonglong2 bh = *(const ulonglong2*)&Bs[buf][kk][64 + tx * 4];
            u64 bb[4] = {bl.x, bl.y, bh.x, bh.y};
            float ar8[8] = {a0.x, a0.y, a0.z, a0.w, a1.x, a1.y, a1.z, a1.w};
#pragma unroll
            for (int r = 0; r < 8; r++) {
                u64 ad = dup2(ar8[r]);
#pragma unroll
                for (int cp = 0; cp < 4; cp++)
                    acc[r][cp] = fma2(ad, bb[cp], acc[r][cp]);
            }
        }
        if (c < NCH - 1) {
            const int nb = (c + 1) & 1;
#pragma unroll
            for (int it = 0; it < 2; it++) {
                int row = a_row0 + it * 64;
                As[nb][a_kq + 0][row] = ra[it].x;
                As[nb][a_kq + 1][row] = ra[it].y;
                As[nb][a_kq + 2][row] = ra[it].z;
                As[nb][a_kq + 3][row] = ra[it].w;
                *(float4*)&Bs[nb][b_k0 + it * 8][b_n] = rb[it];
            }
        }
    }

    // epilogue
#pragma unroll
    for (int r = 0; r < 8; r++) {
        float c0, c1, c2, c3, c4, c5, c6, c7;
        unpack2(acc[r][0], c0, c1); unpack2(acc[r][1], c2, c3);
        unpack2(acc[r][2], c4, c5); unpack2(acc[r][3], c6, c7);
        float4 lo = make_float4(c0, c1, c2, c3);
        float4 hi = make_float4(c4, c5, c6, c7);
        int row = ((r >> 2) * 64) + ty * 4 + (r & 3);
        int m = m0 + row;
        if (headed) {
            int bi = m >> 10, si = m & 1023, h0 = n0 >> 6;
            *(float4*)&O[((size_t)(bi * H_ + h0) * S_ + si) * DH_ + tx * 4] = lo;
            *(float4*)&O[((size_t)(bi * H_ + h0 + 1) * S_ + si) * DH_ + tx * 4] = hi;
        } else {
            *(float4*)&O[(size_t)m * 512 + n0 + tx * 4] = lo;
            *(float4*)&O[(size_t)m * 512 + n0 + 64 + tx * 4] = hi;
        }
    }
}

// ===========================================================================
// Fused causal attention with skewed relative bias, f32x2 inner loops.
// bias(i,j) = q_i . rel[:, S-1-i+j]  for j <= i
// ===========================================================================
__device__ __forceinline__ float rmax16(float v) {
#pragma unroll
    for (int o = 8; o; o >>= 1) v = fmaxf(v, __shfl_xor_sync(0xffffffffu, v, o, 16));
    return v;
}
__device__ __forceinline__ float rsum16(float v) {
#pragma unroll
    for (int o = 8; o; o >>= 1) v += __shfl_xor_sync(0xffffffffu, v, o, 16);
    return v;
}

#define QS(d, i) Qs[(d) * 68 + (i)]
#define KS(d, j) Ks[(d) * 68 + (j)]
#define VS(j, d) Vs[(j) * 68 + (d)]
#define PS(i, j) Ps[(i) * 68 + (j)]
#define RS(d, l) Rs[(d) * 132 + (l)]
#define ATTN_SMEM_BYTES ((4 * 64 * 68 + 64 * 132) * 4)   // 103424 B

__global__ __launch_bounds__(256, 2) void attn_kernel(const float* __restrict__ Q,
                                                      const float* __restrict__ K,
                                                      const float* __restrict__ V,
                                                      const float* __restrict__ rel,
                                                      float* __restrict__ ctx)
{
    extern __shared__ __align__(16) float smf[];
    float* Qs = smf;                // [64][68] transposed: Qs[d][i]
    float* Ks = Qs + 64 * 68;       // [64][68] transposed: Ks[d][j]
    float* Vs = Ks + 64 * 68;       // [64][68] direct:     Vs[j][d]
    float* Ps = Vs + 64 * 68;       // [64][68] probs:      Ps[i][j]
    float* Rs = Ps + 64 * 68;       // [64][132] rel tile:  Rs[d][lc]

    const int qt = (int)gridDim.x - 1 - (int)blockIdx.x;  // heavy tiles first
    const int h = blockIdx.y, b = blockIdx.z;
    const int i0 = qt * 64;
    const int tid = threadIdx.x;
    const int ty = tid >> 4, tx = tid & 15;

    const float* Qb = Q + (size_t)(b * H_ + h) * S_ * DH_;
    const float* Kb = K + (size_t)(b * H_ + h) * S_ * DH_;
    const float* Vb = V + (size_t)(b * H_ + h) * S_ * DH_;
    const float* relh = rel + (size_t)h * DH_ * S_;

    // Load Q tile (transposed)
#pragma unroll
    for (int rep = 0; rep < 4; rep++) {
        int lin = rep * 256 + tid;
        int i = lin >> 4, sd = (lin & 15) * 4;
        float4 v = *(const float4*)&Qb[(i0 + i) * DH_ + sd];
        QS(sd + 0, i) = v.x; QS(sd + 1, i) = v.y;
        QS(sd + 2, i) = v.z; QS(sd + 3, i) = v.w;
    }

    float mrow[4], lrow[4];
    u64 acc2[4][2];
#pragma unroll
    for (int r = 0; r < 4; r++) {
        mrow[r] = -1e30f;
        lrow[r] = 0.f;
        acc2[r][0] = 0ull; acc2[r][1] = 0ull;
    }

    const int bm3 = 60 + 4 * tx - 4 * ty;  // lc index of rv[0]

    for (int jt = 0; jt <= qt; jt++) {
        const int j0 = jt * 64;
        __syncthreads();  // protect Ps/Vs reads of previous iteration

        // Load K (transposed) and V (direct)
#pragma unroll
        for (int rep = 0; rep < 4; rep++) {
            int lin = rep * 256 + tid;
            int j = lin >> 4, sd = (lin & 15) * 4;
            float4 kv = *(const float4*)&Kb[(j0 + j) * DH_ + sd];
            KS(sd + 0, j) = kv.x; KS(sd + 1, j) = kv.y;
            KS(sd + 2, j) = kv.z; KS(sd + 3, j) = kv.w;
            float4 vv = *(const float4*)&Vb[(j0 + j) * DH_ + sd];
            *(float4*)&VS(j, sd) = vv;
        }
        // Load rel tile: columns cbase..cbase+127 of rel[h]
        {
            const int cbase = S_ - 64 - i0 + j0;
#pragma unroll
            for (int rep = 0; rep < 32; rep++) {
                int lin = rep * 256 + tid;
                int d = lin >> 7, lc = lin & 127;
                int c = cbase + lc;
                RS(d, lc) = (c < S_) ? relh[d * S_ + c] : 0.f;
            }
        }
        __syncthreads();

        // S tile: s = q.(k + rel_shifted), packed over column pairs
        u64 s2[4][2];
#pragma unroll
        for (int r = 0; r < 4; r++) { s2[r][0] = 0ull; s2[r][1] = 0ull; }

#pragma unroll 4
        for (int d = 0; d < 64; d++) {
            float4 a4 = *(const float4*)&QS(d, ty * 4);
            ulonglong2 kk = *(const ulonglong2*)&Ks[d * 68 + tx * 4];
            float4 rA = *(const float4*)&Rs[d * 132 + bm3];
            float4 rB = *(const float4*)&Rs[d * 132 + bm3 + 4];
            u64 rvp[6];
            rvp[0] = pack2(rA.x, rA.y);
            rvp[1] = pack2(rA.y, rA.z);
            rvp[2] = pack2(rA.z, rA.w);
            rvp[3] = pack2(rA.w, rB.x);
            rvp[4] = pack2(rB.x, rB.y);
            rvp[5] = pack2(rB.y, rB.z);
            float av[4] = {a4.x, a4.y, a4.z, a4.w};
#pragma unroll
            for (int r = 0; r < 4; r++) {
                u64 ad = dup2(av[r]);
                s2[r][0] = fma2(ad, add2(kk.x, rvp[3 - r]), s2[r][0]);
                s2[r][1] = fma2(ad, add2(kk.y, rvp[5 - r]), s2[r][1]);
            }
        }

        float s[4][4];
#pragma unroll
        for (int r = 0; r < 4; r++) {
            unpack2(s2[r][0], s[r][0], s[r][1]);
            unpack2(s2[r][1], s[r][2], s[r][3]);
        }

        // Causal mask + scale
#pragma unroll
        for (int r = 0; r < 4; r++) {
            int gi = i0 + ty * 4 + r;
#pragma unroll
            for (int c = 0; c < 4; c++) {
                int gj = j0 + tx * 4 + c;
                s[r][c] = (gj > gi) ? -INFINITY : s[r][c] * SCALE_;
            }
        }

        // Online softmax update
#pragma unroll
        for (int r = 0; r < 4; r++) {
            float tm = fmaxf(fmaxf(s[r][0], s[r][1]), fmaxf(s[r][2], s[r][3]));
            tm = rmax16(tm);
            float nm = fmaxf(mrow[r], tm);
            float al = __expf(mrow[r] - nm);
            float p0 = __expf(s[r][0] - nm);
            float p1 = __expf(s[r][1] - nm);
            float p2 = __expf(s[r][2] - nm);
            float p3 = __expf(s[r][3] - nm);
            float rs = rsum16(p0 + p1 + p2 + p3);
            lrow[r] = lrow[r] * al + rs;
            mrow[r] = nm;
            u64 al2 = dup2(al);
            acc2[r][0] = mul2(acc2[r][0], al2);
            acc2[r][1] = mul2(acc2[r][1], al2);
            PS(ty * 4 + r, tx * 4 + 0) = p0;
            PS(ty * 4 + r, tx * 4 + 1) = p1;
            PS(ty * 4 + r, tx * 4 + 2) = p2;
            PS(ty * 4 + r, tx * 4 + 3) = p3;
        }
        __syncthreads();

        // acc += P @ V, packed over column pairs
#pragma unroll 8
        for (int j = 0; j < 64; j++) {
            float p_[4];
#pragma unroll
            for (int r = 0; r < 4; r++) p_[r] = PS(ty * 4 + r, j);
            ulonglong2 vv = *(const ulonglong2*)&Vs[j * 68 + tx * 4];
#pragma unroll
            for (int r = 0; r < 4; r++) {
                u64 pd = dup2(p_[r]);
                acc2[r][0] = fma2(pd, vv.x, acc2[r][0]);
                acc2[r][1] = fma2(pd, vv.y, acc2[r][1]);
            }
        }
    }

    // Write ctx in [B, S, H*DH] layout for the output projection GEMM
#pragma unroll
    for (int r = 0; r < 4; r++) {
        float inv = 1.f / lrow[r];
        float o0, o1, o2, o3;
        unpack2(acc2[r][0], o0, o1);
        unpack2(acc2[r][1], o2, o3);
        int gi = i0 + ty * 4 + r;
        float4 o = make_float4(o0 * inv, o1 * inv, o2 * inv, o3 * inv);
        *(float4*)&g_C[((size_t)b * S_ + gi) * D_ + h * DH_ + tx * 4] = o;
    }
}

// ===========================================================================
extern "C" void kernel_launch(void* const* d_in, const int* in_sizes, int n_in,
                              void* d_out, int out_size)
{
    (void)in_sizes; (void)n_in; (void)out_size;
    const float* queries = (const float*)d_in[0];
    const float* keys    = (const float*)d_in[1];
    const float* values  = (const float*)d_in[2];
    // d_in[3] = mask: causal, implemented analytically
    const float* Wq = (const float*)d_in[4];
    const float* Wk = (const float*)d_in[5];
    const float* Wv = (const float*)d_in[6];
    const float* Wo = (const float*)d_in[7];
    const float* rel = (const float*)d_in[8];

    float *Qp, *Kp, *Vp, *Cp;
    cudaGetSymbolAddress((void**)&Qp, g_Q);
    cudaGetSymbolAddress((void**)&Kp, g_K);
    cudaGetSymbolAddress((void**)&Vp, g_V);
    cudaGetSymbolAddress((void**)&Cp, g_C);

    cudaFuncSetAttribute(attn_kernel, cudaFuncAttributeMaxDynamicSharedMemorySize,
                         ATTN_SMEM_BYTES);

    // fused Q/K/V projections (grid.z selects tensor)
    gemm_f2<<<dim3(4, 32, 3), 256>>>(
        queries, keys, values, Wq, Wk, Wv, Qp, Kp, Vp, 1);

    attn_kernel<<<dim3(16, H_, B_), 256, ATTN_SMEM_BYTES>>>(Qp, Kp, Vp, rel, Cp);

    // output projection
    gemm_f2<<<dim3(4, 32, 1), 256>>>(
        Cp, Cp, Cp, Wo, Wo, Wo, (float*)d_out, (float*)d_out, (float*)d_out, 0);
}